// round 3
// baseline (speedup 1.0000x reference)
#include <cuda_runtime.h>

// RNN: h_t = tanh([x_t, h_{t-1}] @ W_cell + b_cell), logits = h_T @ W_out + b_out
// B=4096, T=128, D=128, H=150, O=10.
//
// Persistent-CTA, 320 threads, packed fp32 FFMA2 (fma.rn.f32x2).
// Accumulators pack pairs over the HIDDEN (j) dimension:
//   - W pairs are native (consecutive j in SMEM)  -> zero movs
//   - h stored DUPLICATED in SMEM ((h,h) pairs)   -> zero movs for the h-part
//   - x-part pays 4 dup-movs per k (128 of 278 k's)

#define T_SEQ   128
#define D_IN    128
#define H_HID   150
#define O_OUT   10
#define KDIM    (D_IN + H_HID)   // 278
#define JW      152              // W column count (H padded to mult of 4)
#define B_BLK   32
#define NTHREADS 320             // jg = tid/8 (0..39, 38..39 pad), bg = tid%8

// SMEM layout (in floats)
#define W_FLOATS    (KDIM * JW)          // 42256
#define OFF_STUB    (W_FLOATS)           // 4 floats, zero (W stub for jg>=38)
#define OFF_BIAS    (OFF_STUB + 4)       // 160 floats
#define OFF_AX      (OFF_BIAS + 160)     // 128 rows x 36 floats (x[k][b])
#define AX_STRIDE   36
#define OFF_AH      (OFF_AX + 128 * AX_STRIDE)  // 160 rows x 68 floats (dup'd h)
#define AH_STRIDE   68
#define SMEM_FLOATS (OFF_AH + 160 * AH_STRIDE)  // 57908 floats = 231632 B

typedef unsigned long long ull;

__device__ __forceinline__ ull fma2(ull a, ull b, ull c) {
    ull d;
    asm("fma.rn.f32x2 %0, %1, %2, %3;" : "=l"(d) : "l"(a), "l"(b), "l"(c));
    return d;
}
__device__ __forceinline__ ull packdup(float w) {
    ull d;
    asm("mov.b64 %0, {%1, %2};" : "=l"(d) : "f"(w), "f"(w));
    return d;
}
__device__ __forceinline__ void unpack2(ull v, float& lo, float& hi) {
    asm("mov.b64 {%0, %1}, %2;" : "=f"(lo), "=f"(hi) : "l"(v));
}

// dup'd-h float index for batch element b: 2 floats per value, 16B gap per 128B
__device__ __forceinline__ int hdup_idx(int b) {
    return 2 * b + (((8 * b) >> 7) << 2);
}

__global__ void __launch_bounds__(NTHREADS, 1)
rnn_ffma2j_kernel(const float* __restrict__ X,
                  const float* __restrict__ Wc,
                  const float* __restrict__ bc,
                  const float* __restrict__ Wo,
                  const float* __restrict__ bo,
                  float* __restrict__ out)
{
    extern __shared__ float smem[];
    float* Wsh  = smem;
    float* stub = smem + OFF_STUB;
    float* bsh  = smem + OFF_BIAS;
    float* Ax   = smem + OFF_AX;
    float* Ah   = smem + OFF_AH;

    const int tid = threadIdx.x;
    const long ctaB0 = (long)blockIdx.x * B_BLK;
    const float* Xb = X + ctaB0 * T_SEQ * D_IN;

    // ---- one-time loads ----
    for (int i = tid; i < W_FLOATS; i += NTHREADS) {
        int k = i / JW;
        int j = i - k * JW;
        Wsh[i] = (j < H_HID) ? Wc[k * H_HID + j] : 0.0f;
    }
    if (tid < 4) stub[tid] = 0.0f;
    for (int j = tid; j < 160; j += NTHREADS)
        bsh[j] = (j < H_HID) ? bc[j] : 0.0f;
    for (int i = tid; i < 160 * AH_STRIDE; i += NTHREADS)
        Ah[i] = 0.0f;                                // h0 = 0 (dup region)

    // x_0 transposed into Ax[k][b]
#pragma unroll
    for (int s = 0; s < 4; s++) {
        int i = tid + s * NTHREADS;
        if (i < B_BLK * (D_IN / 4)) {       // 1024 float4s
            int r = i >> 5;                 // batch row
            int c = i & 31;                 // float4 col
            float4 v = *(const float4*)&Xb[(long)r * T_SEQ * D_IN + c * 4];
            Ax[(c * 4 + 0) * AX_STRIDE + r] = v.x;
            Ax[(c * 4 + 1) * AX_STRIDE + r] = v.y;
            Ax[(c * 4 + 2) * AX_STRIDE + r] = v.z;
            Ax[(c * 4 + 3) * AX_STRIDE + r] = v.w;
        }
    }
    __syncthreads();

    const int bg = tid & 7;         // 0..7  -> 4 batch rows each
    const int jg = tid >> 3;        // 0..39 -> 4 hidden cols each (38,39 pad)
    const int b0 = bg * 4;
    const int j0 = jg * 4;

    const float* wbase = (jg < 38) ? (Wsh + j0) : stub;
    const int    wstep = (jg < 38) ? JW : 0;
    const float4 bias  = *(const float4*)&bsh[j0];

    const int ah1 = hdup_idx(b0);       // first dup pair chunk (b0, b0+1)
    const int ah2 = hdup_idx(b0 + 2);   // second chunk (b0+2, b0+3)

    for (int t = 0; t < T_SEQ; t++) {
        // prefetch x_{t+1} into registers
        float4 xr[4];
        const bool havex = (t + 1 < T_SEQ);
        if (havex) {
#pragma unroll
            for (int s = 0; s < 4; s++) {
                int i = tid + s * NTHREADS;
                if (i < B_BLK * (D_IN / 4)) {
                    int r = i >> 5;
                    int c = i & 31;
                    xr[s] = *(const float4*)&Xb[(long)r * T_SEQ * D_IN + (long)(t + 1) * D_IN + c * 4];
                }
            }
        }

        // acc[jp][bb]: pair (j0+2jp, j0+2jp+1) for batch b0+bb
        ull acc[2][4];
#pragma unroll
        for (int jp = 0; jp < 2; jp++)
#pragma unroll
            for (int bb = 0; bb < 4; bb++)
                acc[jp][bb] = 0ULL;

        // ---- x-part: k = 0..127 (a-dup via movs) ----
#pragma unroll 4
        for (int k = 0; k < D_IN; k++) {
            ulonglong2 wp = *(const ulonglong2*)(wbase + (size_t)k * wstep);
            float4 av = *(const float4*)&Ax[k * AX_STRIDE + b0];
            ull a0 = packdup(av.x), a1 = packdup(av.y);
            ull a2 = packdup(av.z), a3 = packdup(av.w);
            acc[0][0] = fma2(a0, wp.x, acc[0][0]);
            acc[0][1] = fma2(a1, wp.x, acc[0][1]);
            acc[0][2] = fma2(a2, wp.x, acc[0][2]);
            acc[0][3] = fma2(a3, wp.x, acc[0][3]);
            acc[1][0] = fma2(a0, wp.y, acc[1][0]);
            acc[1][1] = fma2(a1, wp.y, acc[1][1]);
            acc[1][2] = fma2(a2, wp.y, acc[1][2]);
            acc[1][3] = fma2(a3, wp.y, acc[1][3]);
        }

        // ---- h-part: k = 128..277 (a-dup native from Ah) ----
#pragma unroll 4
        for (int r = 0; r < H_HID; r++) {
            ulonglong2 wp = *(const ulonglong2*)(wbase + (size_t)(D_IN + r) * wstep);
            ulonglong2 aA = *(const ulonglong2*)&Ah[r * AH_STRIDE + ah1]; // (a0,a0),(a1,a1)
            ulonglong2 aB = *(const ulonglong2*)&Ah[r * AH_STRIDE + ah2]; // (a2,a2),(a3,a3)
            acc[0][0] = fma2(aA.x, wp.x, acc[0][0]);
            acc[0][1] = fma2(aA.y, wp.x, acc[0][1]);
            acc[0][2] = fma2(aB.x, wp.x, acc[0][2]);
            acc[0][3] = fma2(aB.y, wp.x, acc[0][3]);
            acc[1][0] = fma2(aA.x, wp.y, acc[1][0]);
            acc[1][1] = fma2(aA.y, wp.y, acc[1][1]);
            acc[1][2] = fma2(aB.x, wp.y, acc[1][2]);
            acc[1][3] = fma2(aB.y, wp.y, acc[1][3]);
        }

        __syncthreads();   // all reads of Ax/Ah for step t done

        // h_new = tanh(acc + bias) -> Ah (duplicated pairs)
        const float bj[4] = {bias.x, bias.y, bias.z, bias.w};
#pragma unroll
        for (int jp = 0; jp < 2; jp++) {
#pragma unroll
            for (int bb = 0; bb < 4; bb++) {
                float lo, hi;
                unpack2(acc[jp][bb], lo, hi);
                float h0 = tanhf(lo + bj[2 * jp]);
                float h1 = tanhf(hi + bj[2 * jp + 1]);
                int b = b0 + bb;
                *(ull*)&Ah[(j0 + 2 * jp)     * AH_STRIDE + hdup_idx(b)] = packdup(h0);
                *(ull*)&Ah[(j0 + 2 * jp + 1) * AH_STRIDE + hdup_idx(b)] = packdup(h1);
            }
        }

        // store prefetched x_{t+1}
        if (havex) {
#pragma unroll
            for (int s = 0; s < 4; s++) {
                int i = tid + s * NTHREADS;
                if (i < B_BLK * (D_IN / 4)) {
                    int r = i >> 5;
                    int c = i & 31;
                    Ax[(c * 4 + 0) * AX_STRIDE + r] = xr[s].x;
                    Ax[(c * 4 + 1) * AX_STRIDE + r] = xr[s].y;
                    Ax[(c * 4 + 2) * AX_STRIDE + r] = xr[s].z;
                    Ax[(c * 4 + 3) * AX_STRIDE + r] = xr[s].w;
                }
            }
        }
        __syncthreads();
    }

    // ---- classifier head: 320 threads == 32 batch * 10 outputs ----
    {
        const int b = tid / O_OUT;
        const int o = tid - b * O_OUT;
        const int hb = hdup_idx(b);     // lo half holds h
        float s = bo[o];
#pragma unroll 5
        for (int j = 0; j < H_HID; j++)
            s += Ah[j * AH_STRIDE + hb] * Wo[j * O_OUT + o];
        out[(ctaB0 + b) * O_OUT + o] = s;
    }
}

extern "C" void kernel_launch(void* const* d_in, const int* in_sizes, int n_in,
                              void* d_out, int out_size)
{
    const float* X  = (const float*)d_in[0];
    const float* Wc = (const float*)d_in[1];
    const float* bc = (const float*)d_in[2];
    const float* Wo = (const float*)d_in[3];
    const float* bo = (const float*)d_in[4];
    float* out = (float*)d_out;

    const int B = in_sizes[0] / (T_SEQ * D_IN);
    const size_t smem_bytes = (size_t)SMEM_FLOATS * sizeof(float);  // 231632

    cudaFuncSetAttribute(rnn_ffma2j_kernel,
                         cudaFuncAttributeMaxDynamicSharedMemorySize,
                         (int)smem_bytes);

    rnn_ffma2j_kernel<<<B / B_BLK, NTHREADS, smem_bytes>>>(X, Wc, bc, Wo, bo, out);
}

// round 5
// speedup vs baseline: 3.4772x; 3.4772x over previous
#include <cuda_runtime.h>
#include <cuda_bf16.h>
#include <cstdint>

// RNN h_t = tanh([x_t,h_{t-1}]@Wc + bc); out = h_T@Wo + bo
// B=4096, T=128, D=128, H=150, O=10.
// Warp-level tensor cores: mma.sync.m16n8k16 bf16, 3-pass (hi*hi + hi*lo + lo*hi).
// 128 CTAs x 32 batch rows, 256 threads (2 M-tiles x 4 N-groups x 5 n8-tiles).
// W^T (n-major, bf16 hi/lo) + A ([x|h], bf16 hi/lo) in SMEM, fp32 acc in regs.

#define T_SEQ 128
#define D_IN  128
#define H_HID 150
#define O_OUT 10
#define M_BLK 32
#define NPAD  160            // hidden padded to 20 n8-tiles
#define KTILES 18            // K = 128(x) + 150(h) -> 288 = 18 x k16
#define ASTR  296            // row stride in bf16 elems (592 B; 148w = 20 mod 32 -> conflict-free)
#define ASTRB 592

// SMEM byte offsets
#define SM_AH   0
#define SM_AL   18944                 // 32*592
#define SM_WH   37888
#define SM_WL   132608                // + 160*592
#define SM_BIAS 227328                // + 160*592
#define SMEM_BYTES 227968             // + 160*4

typedef unsigned int u32;

__device__ __forceinline__ u32 smem_u32(const void* p) {
    u32 a;
    asm("{ .reg .u64 t; cvta.to.shared.u64 t, %1; cvt.u32.u64 %0, t; }" : "=r"(a) : "l"(p));
    return a;
}
__device__ __forceinline__ void ldsm_x4(u32* r, u32 addr) {
    asm volatile("ldmatrix.sync.aligned.m8n8.x4.shared.b16 {%0,%1,%2,%3}, [%4];"
        : "=r"(r[0]), "=r"(r[1]), "=r"(r[2]), "=r"(r[3]) : "r"(addr));
}
__device__ __forceinline__ void ldsm_x2(u32* r, u32 addr) {
    asm volatile("ldmatrix.sync.aligned.m8n8.x2.shared.b16 {%0,%1}, [%2];"
        : "=r"(r[0]), "=r"(r[1]) : "r"(addr));
}
__device__ __forceinline__ void mma16816(float* c, const u32* a, u32 b0, u32 b1) {
    asm volatile("mma.sync.aligned.m16n8k16.row.col.f32.bf16.bf16.f32 "
        "{%0,%1,%2,%3}, {%4,%5,%6,%7}, {%8,%9}, {%0,%1,%2,%3};"
        : "+f"(c[0]), "+f"(c[1]), "+f"(c[2]), "+f"(c[3])
        : "r"(a[0]), "r"(a[1]), "r"(a[2]), "r"(a[3]), "r"(b0), "r"(b1));
}
// pack (lo=a, hi=b) into bf16x2 (matches vetted CVT_BF16X2_F32 operand order)
__device__ __forceinline__ u32 cvt2(float a, float b) {
    u32 r;
    asm("cvt.rn.bf16x2.f32 %0, %1, %2;" : "=r"(r) : "f"(b), "f"(a));
    return r;
}
__device__ __forceinline__ float bfr(float x) {           // bf16 round-trip
    return __bfloat162float(__float2bfloat16(x));
}

__global__ void __launch_bounds__(256, 1)
rnn_hmma_kernel(const float* __restrict__ X,
                const float* __restrict__ Wc,
                const float* __restrict__ bc,
                const float* __restrict__ Wo,
                const float* __restrict__ bo,
                float* __restrict__ out)
{
    extern __shared__ char smem[];
    const u32 sb = smem_u32(smem);
    const int tid  = threadIdx.x;
    const int lane = tid & 31;
    const int warp = tid >> 5;
    const int wm = warp >> 2;          // 0..1  (m-tile)
    const int wn = warp & 3;           // 0..3  (n-group: 5 n8-tiles)
    const long ctaB0 = (long)blockIdx.x * M_BLK;

    // ================= one-time init =================
    // W^T hi/lo: row n (0..159), col k (0..295). valid (n<150, k<278), else 0.
    for (int i = tid; i < NPAD * ASTR; i += 256) {
        int n = i / ASTR, k = i - n * ASTR;
        float v = (n < H_HID && k < 278) ? Wc[k * H_HID + n] : 0.0f;
        float h = bfr(v);
        u32 off = (u32)n * ASTRB + (u32)k * 2;
        *(__nv_bfloat16*)(smem + SM_WH + off) = __float2bfloat16(h);
        *(__nv_bfloat16*)(smem + SM_WL + off) = __float2bfloat16(v - h);
    }
    for (int n = tid; n < NPAD; n += 256)
        *(float*)(smem + SM_BIAS + n * 4) = (n < H_HID) ? bc[n] : 0.0f;
    // zero A (hi+lo): x region overwritten below, h region must start at 0
    for (int i = tid * 16; i < 2 * M_BLK * ASTRB; i += 256 * 16)
        *(float4*)(smem + SM_AH + i) = make_float4(0.f, 0.f, 0.f, 0.f);
    __syncthreads();

    // x loader mapping: each thread owns (row m, 16 k-values)
    const int xm = tid >> 3;            // 0..31
    const int xk = (tid & 7) * 16;      // 0,16,...,112
    const float* Xrow = X + (ctaB0 + xm) * (long)T_SEQ * D_IN + xk;
    const u32 xdstH = sb + SM_AH + (u32)xm * ASTRB + (u32)xk * 2;
    const u32 xdstL = xdstH + (SM_AL - SM_AH);

    // store x(0)
    {
        float4 v[4];
#pragma unroll
        for (int q = 0; q < 4; q++) v[q] = *(const float4*)(Xrow + 4 * q);
        u32 hh[8], ll[8];
#pragma unroll
        for (int q = 0; q < 4; q++) {
            float hx = bfr(v[q].x), hy = bfr(v[q].y), hz = bfr(v[q].z), hw = bfr(v[q].w);
            hh[2*q]   = cvt2(hx, hy);  hh[2*q+1] = cvt2(hz, hw);
            ll[2*q]   = cvt2(v[q].x - hx, v[q].y - hy);
            ll[2*q+1] = cvt2(v[q].z - hz, v[q].w - hw);
        }
        *(uint4*)(smem + (xdstH - sb))      = *(uint4*)&hh[0];
        *(uint4*)(smem + (xdstH - sb) + 16) = *(uint4*)&hh[4];
        *(uint4*)(smem + (xdstL - sb))      = *(uint4*)&ll[0];
        *(uint4*)(smem + (xdstL - sb) + 16) = *(uint4*)&ll[4];
    }
    __syncthreads();

    // ============ per-lane ldmatrix base addresses ============
    const int mat = lane >> 3, r8 = lane & 7;
    // A: mats {m0..7@k0, m8..15@k0, m0..7@k8, m8..15@k8}
    const u32 aBaseH = sb + SM_AH + (u32)(16 * wm + ((mat & 1) << 3) + r8) * ASTRB
                       + (u32)((mat >> 1) << 3) * 2;
    const u32 aBaseL = aBaseH + (SM_AL - SM_AH);
    // B pair-of-ntiles x4: mats {n0..7@k0, n0..7@k8, n8..15@k0, n8..15@k8}
    const int nb = 40 * wn;
    const u32 bBase1 = sb + SM_WH + (u32)(nb + ((mat >> 1) << 3) + r8) * ASTRB
                       + (u32)((mat & 1) << 3) * 2;
    const u32 bBase2 = bBase1 + 16 * ASTRB;
    // B x2 (5th n-tile): mats {n..n+7@k0, n..n+7@k8} (lanes>=16 addrs benign)
    const u32 bBase3 = sb + SM_WH + (u32)(nb + 32 + r8) * ASTRB + (u32)((mat & 1) << 3) * 2;
    const u32 WLOFF = SM_WL - SM_WH;

    // epilogue mapping: lane -> (m0, n per frag)
    const int eg = lane >> 2, et2 = (lane & 3) * 2;
    const int em0 = 16 * wm + eg;

    float c[5][4];
#pragma unroll
    for (int j = 0; j < 5; j++)
#pragma unroll
        for (int q = 0; q < 4; q++) c[j][q] = 0.0f;

    // ================= time loop =================
    for (int t = 0; t < T_SEQ; t++) {
        // prefetch x(t+1) (LDGs issue early; consumed after the sync)
        float4 v[4];
        const bool havex = (t + 1 < T_SEQ);
        if (havex) {
            const float* xp = Xrow + (long)(t + 1) * D_IN;
#pragma unroll
            for (int q = 0; q < 4; q++) v[q] = *(const float4*)(xp + 4 * q);
        }

        // ---- K loop: 18 tiles x (A hi/lo + B hi/lo loads, 15 mma) ----
#pragma unroll 3
        for (int kt = 0; kt < KTILES; kt++) {
            const u32 ko = (u32)kt * 32;
            u32 a[4], al[4], bh1[4], bh2[4], bh3[2], bl1[4], bl2[4], bl3[2];
            ldsm_x4(a,   aBaseH + ko);
            ldsm_x4(al,  aBaseL + ko);
            ldsm_x4(bh1, bBase1 + ko);
            ldsm_x4(bh2, bBase2 + ko);
            ldsm_x2(bh3, bBase3 + ko);
            ldsm_x4(bl1, bBase1 + WLOFF + ko);
            ldsm_x4(bl2, bBase2 + WLOFF + ko);
            ldsm_x2(bl3, bBase3 + WLOFF + ko);
            // pass 1: A_hi * B_hi
            mma16816(c[0], a, bh1[0], bh1[1]);
            mma16816(c[1], a, bh1[2], bh1[3]);
            mma16816(c[2], a, bh2[0], bh2[1]);
            mma16816(c[3], a, bh2[2], bh2[3]);
            mma16816(c[4], a, bh3[0], bh3[1]);
            // pass 2: A_hi * B_lo
            mma16816(c[0], a, bl1[0], bl1[1]);
            mma16816(c[1], a, bl1[2], bl1[3]);
            mma16816(c[2], a, bl2[0], bl2[1]);
            mma16816(c[3], a, bl2[2], bl2[3]);
            mma16816(c[4], a, bl3[0], bl3[1]);
            // pass 3: A_lo * B_hi
            mma16816(c[0], al, bh1[0], bh1[1]);
            mma16816(c[1], al, bh1[2], bh1[3]);
            mma16816(c[2], al, bh2[0], bh2[1]);
            mma16816(c[3], al, bh2[2], bh2[3]);
            mma16816(c[4], al, bh3[0], bh3[1]);
        }

        __syncthreads();   // all ldmatrix reads of A done

        // ---- epilogue: h = tanh(acc + bias) -> A (hi/lo), reset acc ----
#pragma unroll
        for (int j = 0; j < 5; j++) {
            const int n = nb + 8 * j + et2;
            const float2 bv = *(const float2*)(smem + SM_BIAS + n * 4);
            float h00 = tanhf(c[j][0] + bv.x);
            float h01 = tanhf(c[j][1] + bv.y);
            float h10 = tanhf(c[j][2] + bv.x);
            float h11 = tanhf(c[j][3] + bv.y);
            float r00 = bfr(h00), r01 = bfr(h01), r10 = bfr(h10), r11 = bfr(h11);
            u32 o0 = (u32)em0 * ASTRB + (u32)(D_IN + n) * 2;
            u32 o1 = o0 + 8 * ASTRB;
            *(u32*)(smem + SM_AH + o0) = cvt2(h00, h01);
            *(u32*)(smem + SM_AH + o1) = cvt2(h10, h11);
            *(u32*)(smem + SM_AL + o0) = cvt2(h00 - r00, h01 - r01);
            *(u32*)(smem + SM_AL + o1) = cvt2(h10 - r10, h11 - r11);
            c[j][0] = 0.f; c[j][1] = 0.f; c[j][2] = 0.f; c[j][3] = 0.f;
        }

        // ---- store prefetched x(t+1) ----
        if (havex) {
            u32 hh[8], ll[8];
#pragma unroll
            for (int q = 0; q < 4; q++) {
                float hx = bfr(v[q].x), hy = bfr(v[q].y), hz = bfr(v[q].z), hw = bfr(v[q].w);
                hh[2*q]   = cvt2(hx, hy);  hh[2*q+1] = cvt2(hz, hw);
                ll[2*q]   = cvt2(v[q].x - hx, v[q].y - hy);
                ll[2*q+1] = cvt2(v[q].z - hz, v[q].w - hw);
            }
            *(uint4*)(smem + (xdstH - sb))      = *(uint4*)&hh[0];
            *(uint4*)(smem + (xdstH - sb) + 16) = *(uint4*)&hh[4];
            *(uint4*)(smem + (xdstL - sb))      = *(uint4*)&ll[0];
            *(uint4*)(smem + (xdstL - sb) + 16) = *(uint4*)&ll[4];
        }
        __syncthreads();
    }

    // ================= classifier head =================
    // h(fp32) = A_hi + A_lo; out[b][o] = h . Wo[:,o] + bo[o]
    for (int i = tid; i < M_BLK * O_OUT; i += 256) {
        const int b = i / O_OUT;
        const int o = i - b * O_OUT;
        float s = bo[o];
        const char* rowH = smem + SM_AH + (u32)b * ASTRB + D_IN * 2;
        const char* rowL = smem + SM_AL + (u32)b * ASTRB + D_IN * 2;
#pragma unroll 5
        for (int j = 0; j < H_HID; j++) {
            float hv = __bfloat162float(*(const __nv_bfloat16*)(rowH + 2 * j))
                     + __bfloat162float(*(const __nv_bfloat16*)(rowL + 2 * j));
            s += hv * Wo[j * O_OUT + o];
        }
        out[(ctaB0 + b) * O_OUT + o] = s;
    }
}

extern "C" void kernel_launch(void* const* d_in, const int* in_sizes, int n_in,
                              void* d_out, int out_size)
{
    const float* X  = (const float*)d_in[0];
    const float* Wc = (const float*)d_in[1];
    const float* bc = (const float*)d_in[2];
    const float* Wo = (const float*)d_in[3];
    const float* bo = (const float*)d_in[4];
    float* out = (float*)d_out;

    const int B = in_sizes[0] / (T_SEQ * D_IN);   // 4096

    cudaFuncSetAttribute(rnn_hmma_kernel,
                         cudaFuncAttributeMaxDynamicSharedMemorySize, SMEM_BYTES);

    rnn_hmma_kernel<<<B / M_BLK, 256, SMEM_BYTES>>>(X, Wc, bc, Wo, bo, out);
}

// round 6
// speedup vs baseline: 3.5727x; 1.0275x over previous
#include <cuda_runtime.h>
#include <cuda_bf16.h>
#include <cstdint>

// RNN h_t = tanh([x_t,h_{t-1}]@Wc + bc); out = h_T@Wo + bo
// B=4096, T=128, D=128, H=150, O=10.
// Warp-level tensor cores: mma.sync.m16n8k16 bf16, 3-pass (hi*hi + hi*lo + lo*hi).
// 128 CTAs x 32 batch rows, 256 threads (2 M-tiles x 4 N-groups x 5 n8-tiles).
// R6: full K-unroll, __expf-based tanh, hoisted bias.

#define T_SEQ 128
#define D_IN  128
#define H_HID 150
#define O_OUT 10
#define M_BLK 32
#define NPAD  160
#define KTILES 18
#define ASTR  296            // row stride in bf16 elems (592 B; conflict-free for ldmatrix)
#define ASTRB 592

// SMEM byte offsets
#define SM_AH   0
#define SM_AL   18944                 // 32*592
#define SM_WH   37888
#define SM_WL   132608                // + 160*592
#define SM_BIAS 227328                // + 160*592
#define SMEM_BYTES 227968             // + 160*4

typedef unsigned int u32;

__device__ __forceinline__ u32 smem_u32(const void* p) {
    u32 a;
    asm("{ .reg .u64 t; cvta.to.shared.u64 t, %1; cvt.u32.u64 %0, t; }" : "=r"(a) : "l"(p));
    return a;
}
__device__ __forceinline__ void ldsm_x4(u32* r, u32 addr) {
    asm volatile("ldmatrix.sync.aligned.m8n8.x4.shared.b16 {%0,%1,%2,%3}, [%4];"
        : "=r"(r[0]), "=r"(r[1]), "=r"(r[2]), "=r"(r[3]) : "r"(addr));
}
__device__ __forceinline__ void ldsm_x2(u32* r, u32 addr) {
    asm volatile("ldmatrix.sync.aligned.m8n8.x2.shared.b16 {%0,%1}, [%2];"
        : "=r"(r[0]), "=r"(r[1]) : "r"(addr));
}
__device__ __forceinline__ void mma16816(float* c, const u32* a, u32 b0, u32 b1) {
    asm volatile("mma.sync.aligned.m16n8k16.row.col.f32.bf16.bf16.f32 "
        "{%0,%1,%2,%3}, {%4,%5,%6,%7}, {%8,%9}, {%0,%1,%2,%3};"
        : "+f"(c[0]), "+f"(c[1]), "+f"(c[2]), "+f"(c[3])
        : "r"(a[0]), "r"(a[1]), "r"(a[2]), "r"(a[3]), "r"(b0), "r"(b1));
}
// pack (lo=a, hi=b) into bf16x2
__device__ __forceinline__ u32 cvt2(float a, float b) {
    u32 r;
    asm("cvt.rn.bf16x2.f32 %0, %1, %2;" : "=r"(r) : "f"(b), "f"(a));
    return r;
}
__device__ __forceinline__ float bfr(float x) {           // bf16 round-trip
    return __bfloat162float(__float2bfloat16(x));
}
// fast tanh: 2 MUFU + few ALU, rel err ~3e-6 (vs 1e-3 tolerance)
__device__ __forceinline__ float fast_tanh(float x) {
    float xc = fminf(fmaxf(x, -10.0f), 10.0f);
    float e = __expf(2.0f * xc);
    return __fdividef(e - 1.0f, e + 1.0f);
}

__global__ void __launch_bounds__(256, 1)
rnn_hmma_kernel(const float* __restrict__ X,
                const float* __restrict__ Wc,
                const float* __restrict__ bc,
                const float* __restrict__ Wo,
                const float* __restrict__ bo,
                float* __restrict__ out)
{
    extern __shared__ char smem[];
    const u32 sb = smem_u32(smem);
    const int tid  = threadIdx.x;
    const int lane = tid & 31;
    const int warp = tid >> 5;
    const int wm = warp >> 2;          // 0..1  (m-tile)
    const int wn = warp & 3;           // 0..3  (n-group: 5 n8-tiles)
    const long ctaB0 = (long)blockIdx.x * M_BLK;

    // ================= one-time init =================
    for (int i = tid; i < NPAD * ASTR; i += 256) {
        int n = i / ASTR, k = i - n * ASTR;
        float v = (n < H_HID && k < 278) ? Wc[k * H_HID + n] : 0.0f;
        float h = bfr(v);
        u32 off = (u32)n * ASTRB + (u32)k * 2;
        *(__nv_bfloat16*)(smem + SM_WH + off) = __float2bfloat16(h);
        *(__nv_bfloat16*)(smem + SM_WL + off) = __float2bfloat16(v - h);
    }
    for (int n = tid; n < NPAD; n += 256)
        *(float*)(smem + SM_BIAS + n * 4) = (n < H_HID) ? bc[n] : 0.0f;
    for (int i = tid * 16; i < 2 * M_BLK * ASTRB; i += 256 * 16)
        *(float4*)(smem + SM_AH + i) = make_float4(0.f, 0.f, 0.f, 0.f);
    __syncthreads();

    // x loader mapping: each thread owns (row m, 16 k-values)
    const int xm = tid >> 3;
    const int xk = (tid & 7) * 16;
    const float* Xrow = X + (ctaB0 + xm) * (long)T_SEQ * D_IN + xk;
    const u32 xdstH = (u32)(SM_AH) + (u32)xm * ASTRB + (u32)xk * 2;
    const u32 xdstL = xdstH + (SM_AL - SM_AH);

    // store x(0)
    {
        float4 v[4];
#pragma unroll
        for (int q = 0; q < 4; q++) v[q] = *(const float4*)(Xrow + 4 * q);
        u32 hh[8], ll[8];
#pragma unroll
        for (int q = 0; q < 4; q++) {
            float hx = bfr(v[q].x), hy = bfr(v[q].y), hz = bfr(v[q].z), hw = bfr(v[q].w);
            hh[2*q]   = cvt2(hx, hy);  hh[2*q+1] = cvt2(hz, hw);
            ll[2*q]   = cvt2(v[q].x - hx, v[q].y - hy);
            ll[2*q+1] = cvt2(v[q].z - hz, v[q].w - hw);
        }
        *(uint4*)(smem + xdstH)      = *(uint4*)&hh[0];
        *(uint4*)(smem + xdstH + 16) = *(uint4*)&hh[4];
        *(uint4*)(smem + xdstL)      = *(uint4*)&ll[0];
        *(uint4*)(smem + xdstL + 16) = *(uint4*)&ll[4];
    }
    __syncthreads();

    // ============ per-lane ldmatrix base addresses ============
    const int mat = lane >> 3, r8 = lane & 7;
    const u32 aBaseH = sb + SM_AH + (u32)(16 * wm + ((mat & 1) << 3) + r8) * ASTRB
                       + (u32)((mat >> 1) << 3) * 2;
    const u32 aBaseL = aBaseH + (SM_AL - SM_AH);
    const int nb = 40 * wn;
    const u32 bBase1 = sb + SM_WH + (u32)(nb + ((mat >> 1) << 3) + r8) * ASTRB
                       + (u32)((mat & 1) << 3) * 2;
    const u32 bBase2 = bBase1 + 16 * ASTRB;
    const u32 bBase3 = sb + SM_WH + (u32)(nb + 32 + r8) * ASTRB + (u32)((mat & 1) << 3) * 2;
    const u32 WLOFF = SM_WL - SM_WH;

    // epilogue mapping + hoisted bias (constant over time)
    const int eg = lane >> 2, et2 = (lane & 3) * 2;
    const int em0 = 16 * wm + eg;
    float2 bias_r[5];
#pragma unroll
    for (int j = 0; j < 5; j++)
        bias_r[j] = *(const float2*)(smem + SM_BIAS + (nb + 8 * j + et2) * 4);

    float c[5][4];
#pragma unroll
    for (int j = 0; j < 5; j++)
#pragma unroll
        for (int q = 0; q < 4; q++) c[j][q] = 0.0f;

    // ================= time loop =================
    for (int t = 0; t < T_SEQ; t++) {
        // prefetch x(t+1)
        float4 v[4];
        const bool havex = (t + 1 < T_SEQ);
        if (havex) {
            const float* xp = Xrow + (long)(t + 1) * D_IN;
#pragma unroll
            for (int q = 0; q < 4; q++) v[q] = *(const float4*)(xp + 4 * q);
        }

        // ---- K loop: FULL unroll; ptxas pipelines ldsm ahead of mma ----
#pragma unroll
        for (int kt = 0; kt < KTILES; kt++) {
            const u32 ko = (u32)kt * 32;
            u32 a[4], al[4], bh1[4], bh2[4], bh3[2], bl1[4], bl2[4], bl3[2];
            ldsm_x4(a,   aBaseH + ko);
            ldsm_x4(al,  aBaseL + ko);
            ldsm_x4(bh1, bBase1 + ko);
            ldsm_x4(bh2, bBase2 + ko);
            ldsm_x2(bh3, bBase3 + ko);
            ldsm_x4(bl1, bBase1 + WLOFF + ko);
            ldsm_x4(bl2, bBase2 + WLOFF + ko);
            ldsm_x2(bl3, bBase3 + WLOFF + ko);
            // pass 1: A_hi * B_hi
            mma16816(c[0], a, bh1[0], bh1[1]);
            mma16816(c[1], a, bh1[2], bh1[3]);
            mma16816(c[2], a, bh2[0], bh2[1]);
            mma16816(c[3], a, bh2[2], bh2[3]);
            mma16816(c[4], a, bh3[0], bh3[1]);
            // pass 2: A_hi * B_lo
            mma16816(c[0], a, bl1[0], bl1[1]);
            mma16816(c[1], a, bl1[2], bl1[3]);
            mma16816(c[2], a, bl2[0], bl2[1]);
            mma16816(c[3], a, bl2[2], bl2[3]);
            mma16816(c[4], a, bl3[0], bl3[1]);
            // pass 3: A_lo * B_hi
            mma16816(c[0], al, bh1[0], bh1[1]);
            mma16816(c[1], al, bh1[2], bh1[3]);
            mma16816(c[2], al, bh2[0], bh2[1]);
            mma16816(c[3], al, bh2[2], bh2[3]);
            mma16816(c[4], al, bh3[0], bh3[1]);
        }

        __syncthreads();   // all ldmatrix reads of A done

        // ---- epilogue: h = tanh(acc + bias) -> A (hi/lo), reset acc ----
#pragma unroll
        for (int j = 0; j < 5; j++) {
            const int n = nb + 8 * j + et2;
            float h00 = fast_tanh(c[j][0] + bias_r[j].x);
            float h01 = fast_tanh(c[j][1] + bias_r[j].y);
            float h10 = fast_tanh(c[j][2] + bias_r[j].x);
            float h11 = fast_tanh(c[j][3] + bias_r[j].y);
            float r00 = bfr(h00), r01 = bfr(h01), r10 = bfr(h10), r11 = bfr(h11);
            u32 o0 = (u32)em0 * ASTRB + (u32)(D_IN + n) * 2;
            u32 o1 = o0 + 8 * ASTRB;
            *(u32*)(smem + SM_AH + o0) = cvt2(h00, h01);
            *(u32*)(smem + SM_AH + o1) = cvt2(h10, h11);
            *(u32*)(smem + SM_AL + o0) = cvt2(h00 - r00, h01 - r01);
            *(u32*)(smem + SM_AL + o1) = cvt2(h10 - r10, h11 - r11);
            c[j][0] = 0.f; c[j][1] = 0.f; c[j][2] = 0.f; c[j][3] = 0.f;
        }

        // ---- store prefetched x(t+1) ----
        if (havex) {
            u32 hh[8], ll[8];
#pragma unroll
            for (int q = 0; q < 4; q++) {
                float hx = bfr(v[q].x), hy = bfr(v[q].y), hz = bfr(v[q].z), hw = bfr(v[q].w);
                hh[2*q]   = cvt2(hx, hy);  hh[2*q+1] = cvt2(hz, hw);
                ll[2*q]   = cvt2(v[q].x - hx, v[q].y - hy);
                ll[2*q+1] = cvt2(v[q].z - hz, v[q].w - hw);
            }
            *(uint4*)(smem + xdstH)      = *(uint4*)&hh[0];
            *(uint4*)(smem + xdstH + 16) = *(uint4*)&hh[4];
            *(uint4*)(smem + xdstL)      = *(uint4*)&ll[0];
            *(uint4*)(smem + xdstL + 16) = *(uint4*)&ll[4];
        }
        __syncthreads();
    }

    // ================= classifier head =================
    for (int i = tid; i < M_BLK * O_OUT; i += 256) {
        const int b = i / O_OUT;
        const int o = i - b * O_OUT;
        float s = bo[o];
        const char* rowH = smem + SM_AH + (u32)b * ASTRB + D_IN * 2;
        const char* rowL = smem + SM_AL + (u32)b * ASTRB + D_IN * 2;
#pragma unroll 5
        for (int j = 0; j < H_HID; j++) {
            float hv = __bfloat162float(*(const __nv_bfloat16*)(rowH + 2 * j))
                     + __bfloat162float(*(const __nv_bfloat16*)(rowL + 2 * j));
            s += hv * Wo[j * O_OUT + o];
        }
        out[(ctaB0 + b) * O_OUT + o] = s;
    }
}

extern "C" void kernel_launch(void* const* d_in, const int* in_sizes, int n_in,
                              void* d_out, int out_size)
{
    const float* X  = (const float*)d_in[0];
    const float* Wc = (const float*)d_in[1];
    const float* bc = (const float*)d_in[2];
    const float* Wo = (const float*)d_in[3];
    const float* bo = (const float*)d_in[4];
    float* out = (float*)d_out;

    const int B = in_sizes[0] / (T_SEQ * D_IN);   // 4096

    cudaFuncSetAttribute(rnn_hmma_kernel,
                         cudaFuncAttributeMaxDynamicSharedMemorySize, SMEM_BYTES);

    rnn_hmma_kernel<<<B / M_BLK, 256, SMEM_BYTES>>>(X, Wc, bc, Wo, bo, out);
}